// round 7
// baseline (speedup 1.0000x reference)
#include <cuda_runtime.h>
#include <cuda_bf16.h>

// Problem constants
#define BB 4
#define TT 1024
#define CC 768
#define NH 12
#define HD 64
#define BT (BB*TT)          // 4096
#define N_QKV (3*CC)        // 2304

// Scratch (allocation-free rule: __device__ globals).
// tf32 bit patterns stored in float arrays. 256-byte aligned: cp.async.cg
// needs 16B-aligned global addresses and the language only guarantees 4B.
__device__ __align__(256) float g_q[BB*NH*TT*HD];
__device__ __align__(256) float g_k[BB*NH*TT*HD];
__device__ __align__(256) float g_v[BB*NH*TT*HD];
__device__ __align__(256) float g_y[BT*CC];
__device__ __align__(256) float g_xa[BT*CC];
__device__ __align__(256) float g_wqkva[CC*N_QKV];
__device__ __align__(256) float g_wproja[CC*CC];

// ---------------------------------------------------------------------------
// Helpers
// ---------------------------------------------------------------------------
__device__ __forceinline__ unsigned f2tf32(float f) {
    unsigned r;
    asm("cvt.rna.tf32.f32 %0, %1;" : "=r"(r) : "f"(f));
    return r;
}

__device__ __forceinline__ void mma8(float* c, const unsigned* a, const unsigned* b) {
    asm volatile(
        "mma.sync.aligned.m16n8k8.row.col.f32.tf32.tf32.f32 "
        "{%0,%1,%2,%3}, {%4,%5,%6,%7}, {%8,%9}, {%0,%1,%2,%3};"
        : "+f"(c[0]), "+f"(c[1]), "+f"(c[2]), "+f"(c[3])
        : "r"(a[0]), "r"(a[1]), "r"(a[2]), "r"(a[3]),
          "r"(b[0]), "r"(b[1]));
}

__device__ __forceinline__ unsigned smem_u32(const void* p) {
    return (unsigned)__cvta_generic_to_shared(p);
}

#define CPA(dst, src) asm volatile("cp.async.cg.shared.global [%0], [%1], 16;" :: "r"(dst), "l"(src))
#define CPC()  asm volatile("cp.async.commit_group;")
#define CPW0() asm volatile("cp.async.wait_group 0;")
#define CPW1() asm volatile("cp.async.wait_group 1;")

// ---------------------------------------------------------------------------
// Elementwise fp32 -> tf32 (rna) pre-conversion
// ---------------------------------------------------------------------------
__global__ void cvt_kernel(const float* __restrict__ s, float* __restrict__ d, int n4)
{
    int i = blockIdx.x * blockDim.x + threadIdx.x;
    if (i < n4) {
        float4 v = ((const float4*)s)[i];
        uint4 o = make_uint4(f2tf32(v.x), f2tf32(v.y), f2tf32(v.z), f2tf32(v.w));
        ((uint4*)d)[i] = o;
    }
}

// ---------------------------------------------------------------------------
// GEMM mainloop: cp.async double-buffered, operands pre-converted tf32.
// C tile 128x128, 256 threads / 8 warps (2m x 4n), k-chunk 16.
// ---------------------------------------------------------------------------
#define GA_LD 20
#define GB_LD 136

template<int N_GLOBAL>
__device__ __forceinline__ void gemm_mainloop_ca(
    const float* __restrict__ A, const float* __restrict__ Bm,
    int m0, int n0, unsigned* As, unsigned* Bs, float acc[4][4][4])
{
    const int tid  = threadIdx.x;
    const int warp = tid >> 5;
    const int lane = tid & 31;
    const int g = lane >> 2, t = lane & 3;
    const int wm = warp >> 2;
    const int wn = warp & 3;

    const unsigned aBase = smem_u32(As);
    const unsigned bBase = smem_u32(Bs);

    int aoff[2], boff[2];
    size_t asrc[2], bsrc[2];
    #pragma unroll
    for (int s = 0; s < 2; s++) {
        int idx = tid + s * 256;
        int ar = idx >> 2, ak = (idx & 3) * 4;
        aoff[s] = ar * GA_LD + ak;
        asrc[s] = (size_t)(m0 + ar) * CC + ak;
        int bk = idx >> 5, bn = (idx & 31) * 4;
        boff[s] = bk * GB_LD + bn;
        bsrc[s] = (size_t)bk * N_GLOBAL + n0 + bn;
    }

#define GEMM_ISSUE(k0, buf) do {                                                     \
        CPA(aBase + ((buf)*128*GA_LD + aoff[0])*4u, A + asrc[0] + (k0));             \
        CPA(bBase + ((buf)*16*GB_LD  + boff[0])*4u, Bm + bsrc[0] + (size_t)(k0)*N_GLOBAL); \
        CPA(aBase + ((buf)*128*GA_LD + aoff[1])*4u, A + asrc[1] + (k0));             \
        CPA(bBase + ((buf)*16*GB_LD  + boff[1])*4u, Bm + bsrc[1] + (size_t)(k0)*N_GLOBAL); \
    } while (0)

    GEMM_ISSUE(0, 0);
    CPC();

    const int NIT = CC / 16;
    for (int it = 0; it < NIT; it++) {
        const int cur = it & 1;
        if (it + 1 < NIT) {
            GEMM_ISSUE((it + 1) * 16, cur ^ 1);
            CPC();
            CPW1();
        } else {
            CPW0();
        }
        __syncthreads();

        const unsigned* Ac = As + cur * 128 * GA_LD;
        const unsigned* Bc = Bs + cur * 16 * GB_LD;

        #pragma unroll
        for (int ks = 0; ks < 2; ks++) {
            const int kk = ks * 8;
            unsigned af[4][4], bf[4][2];
            #pragma unroll
            for (int mt = 0; mt < 4; mt++) {
                int r = wm * 64 + mt * 16 + g;
                af[mt][0] = Ac[r * GA_LD + kk + t];
                af[mt][1] = Ac[(r + 8) * GA_LD + kk + t];
                af[mt][2] = Ac[r * GA_LD + kk + t + 4];
                af[mt][3] = Ac[(r + 8) * GA_LD + kk + t + 4];
            }
            #pragma unroll
            for (int nt = 0; nt < 4; nt++) {
                int c = wn * 32 + nt * 8 + g;
                bf[nt][0] = Bc[(kk + t) * GB_LD + c];
                bf[nt][1] = Bc[(kk + t + 4) * GB_LD + c];
            }
            #pragma unroll
            for (int mt = 0; mt < 4; mt++)
                #pragma unroll
                for (int nt = 0; nt < 4; nt++)
                    mma8(acc[mt][nt], af[mt], bf[nt]);
        }
        __syncthreads();
    }
#undef GEMM_ISSUE
}

// ---------------------------------------------------------------------------
// Kernel 1: qkv = x @ Wqkv + bqkv -> head-major q/k/v (stored as tf32 bits;
// softmax scale 1/8 folded into q)
// ---------------------------------------------------------------------------
__global__ __launch_bounds__(256) void qkv_gemm_kernel(
    const float* __restrict__ A,
    const float* __restrict__ Bm,
    const float* __restrict__ bias)
{
    __shared__ unsigned As[2 * 128 * GA_LD];
    __shared__ unsigned Bs[2 * 16 * GB_LD];

    const int tid  = threadIdx.x;
    const int warp = tid >> 5;
    const int lane = tid & 31;
    const int g = lane >> 2, t = lane & 3;
    const int wm = warp >> 2;
    const int wn = warp & 3;
    const int m0 = blockIdx.y * 128;
    const int n0 = blockIdx.x * 128;

    float acc[4][4][4];
    #pragma unroll
    for (int i = 0; i < 4; i++)
        #pragma unroll
        for (int j = 0; j < 4; j++)
            #pragma unroll
            for (int e = 0; e < 4; e++) acc[i][j][e] = 0.f;

    gemm_mainloop_ca<N_QKV>(A, Bm, m0, n0, As, Bs, acc);

    const int which = n0 / CC;
    float* dst = (which == 0) ? g_q : (which == 1) ? g_k : g_v;
    const float sc = (which == 0) ? 0.125f : 1.0f;

    #pragma unroll
    for (int mt = 0; mt < 4; mt++) {
        int r0 = m0 + wm * 64 + mt * 16 + g;
        #pragma unroll
        for (int nt = 0; nt < 4; nt++) {
            int cg = n0 + wn * 32 + nt * 8 + t * 2;
            int c0 = cg - which * CC;
            int h = c0 >> 6, d = c0 & 63;
            float b0v = bias[cg], b1v = bias[cg + 1];
            int b_ = r0 >> 10, t_ = r0 & 1023;
            *(uint2*)&dst[(size_t)(((b_ * NH + h) * TT) + t_) * HD + d] =
                make_uint2(f2tf32((acc[mt][nt][0] + b0v) * sc),
                           f2tf32((acc[mt][nt][1] + b1v) * sc));
            int r1 = r0 + 8;
            b_ = r1 >> 10; t_ = r1 & 1023;
            *(uint2*)&dst[(size_t)(((b_ * NH + h) * TT) + t_) * HD + d] =
                make_uint2(f2tf32((acc[mt][nt][2] + b0v) * sc),
                           f2tf32((acc[mt][nt][3] + b1v) * sc));
        }
    }
}

// ---------------------------------------------------------------------------
// Kernel 3: out = y @ Wproj + bproj (fp32 output)
// ---------------------------------------------------------------------------
__global__ __launch_bounds__(256) void proj_gemm_kernel(
    const float* __restrict__ Bm,
    const float* __restrict__ bias,
    float* __restrict__ out)
{
    __shared__ unsigned As[2 * 128 * GA_LD];
    __shared__ unsigned Bs[2 * 16 * GB_LD];

    const int tid  = threadIdx.x;
    const int warp = tid >> 5;
    const int lane = tid & 31;
    const int g = lane >> 2, t = lane & 3;
    const int wm = warp >> 2;
    const int wn = warp & 3;
    const int m0 = blockIdx.y * 128;
    const int n0 = blockIdx.x * 128;

    float acc[4][4][4];
    #pragma unroll
    for (int i = 0; i < 4; i++)
        #pragma unroll
        for (int j = 0; j < 4; j++)
            #pragma unroll
            for (int e = 0; e < 4; e++) acc[i][j][e] = 0.f;

    gemm_mainloop_ca<CC>(g_y, Bm, m0, n0, As, Bs, acc);

    #pragma unroll
    for (int mt = 0; mt < 4; mt++) {
        int r0 = m0 + wm * 64 + mt * 16 + g;
        #pragma unroll
        for (int nt = 0; nt < 4; nt++) {
            int cg = n0 + wn * 32 + nt * 8 + t * 2;
            float b0v = bias[cg], b1v = bias[cg + 1];
            *(float2*)&out[(size_t)r0 * CC + cg] =
                make_float2(acc[mt][nt][0] + b0v, acc[mt][nt][1] + b1v);
            *(float2*)&out[(size_t)(r0 + 8) * CC + cg] =
                make_float2(acc[mt][nt][2] + b0v, acc[mt][nt][3] + b1v);
        }
    }
}

// ---------------------------------------------------------------------------
// Kernel 2: causal flash attention.
// CTA = (64 q rows, head, batch), 256 threads / 8 warps (4m x 2n).
// K/V double-buffered via cp.async; softmax in registers + small smem exchange.
// ---------------------------------------------------------------------------
#define QS_LD 68
#define PS_LD 68
#define KS_LD 68
#define VS_LD 72

#define ATTN_SMEM ((64*QS_LD + 64*PS_LD + 2*64*KS_LD + 2*64*VS_LD + 64 + 64 + 128 + 128) * 4)

__global__ __launch_bounds__(256) void attn_kernel()
{
    extern __shared__ unsigned smu[];
    unsigned* Qs = smu;                       // [64][QS_LD] tf32 (pre-scaled)
    unsigned* Ps = Qs + 64 * QS_LD;           // [64][PS_LD] tf32
    unsigned* Ks = Ps + 64 * PS_LD;           // 2 x [64 keys][KS_LD d] tf32
    unsigned* Vs = Ks + 2 * 64 * KS_LD;       // 2 x [64 keys][VS_LD d] tf32
    float* mrow = (float*)(Vs + 2 * 64 * VS_LD);  // [64]
    float* lrow = mrow + 64;                  // [64]
    float* pmax = lrow + 64;                  // [64][2]
    float* psum = pmax + 128;                 // [64][2]

    const int tid  = threadIdx.x;
    const int warp = tid >> 5;
    const int lane = tid & 31;
    const int g = lane >> 2, t = lane & 3;
    const int wm = warp >> 1;   // 0..3 (row stripe)
    const int wn = warp & 1;    // 0..1 (col half)
    const int rm = wm * 16;
    const int r0 = rm + g, r1 = rm + g + 8;

    const int qt = gridDim.x - 1 - blockIdx.x;   // heavy tiles first
    const int h  = blockIdx.y;
    const int b  = blockIdx.z;

    const float* qb = g_q + (size_t)((b * NH + h) * TT) * HD;
    const float* kb = g_k + (size_t)((b * NH + h) * TT) * HD;
    const float* vb = g_v + (size_t)((b * NH + h) * TT) * HD;

    const unsigned qB = smem_u32(Qs);
    const unsigned kB = smem_u32(Ks);
    const unsigned vB = smem_u32(Vs);

    int lrw[4], lcc[4];
    #pragma unroll
    for (int s = 0; s < 4; s++) {
        int idx = tid + s * 256;
        lrw[s] = idx >> 4;
        lcc[s] = (idx & 15) * 4;
    }

#define KV_ISSUE(j, buf) do {                                                          \
        _Pragma("unroll")                                                              \
        for (int s = 0; s < 4; s++) {                                                  \
            size_t so = (size_t)((j) * 64 + lrw[s]) * HD + lcc[s];                     \
            CPA(kB + ((buf)*64*KS_LD + lrw[s]*KS_LD + lcc[s])*4u, kb + so);            \
            CPA(vB + ((buf)*64*VS_LD + lrw[s]*VS_LD + lcc[s])*4u, vb + so);            \
        }                                                                              \
    } while (0)

    // Prologue: Q tile + first K/V tile in one async group
    #pragma unroll
    for (int s = 0; s < 4; s++)
        CPA(qB + (lrw[s]*QS_LD + lcc[s])*4u,
            qb + (size_t)(qt * 64 + lrw[s]) * HD + lcc[s]);
    KV_ISSUE(0, 0);
    CPC();

    if (tid < 64) { mrow[tid] = -1e30f; lrow[tid] = 0.f; }

    float o[4][4];
    #pragma unroll
    for (int i = 0; i < 4; i++)
        #pragma unroll
        for (int e = 0; e < 4; e++) o[i][e] = 0.f;

    for (int j0 = 0; j0 <= qt; j0++) {
        const int cur = j0 & 1;
        if (j0 < qt) {
            KV_ISSUE(j0 + 1, cur ^ 1);
            CPC();
            CPW1();
        } else {
            CPW0();
        }
        __syncthreads();

        const unsigned* Kc = Ks + cur * 64 * KS_LD;
        const unsigned* Vc = Vs + cur * 64 * VS_LD;

        // ---- S = Q K^T (scale pre-folded into Q) ----
        float sacc[4][4];
        #pragma unroll
        for (int nt = 0; nt < 4; nt++)
            #pragma unroll
            for (int e = 0; e < 4; e++) sacc[nt][e] = 0.f;

        #pragma unroll
        for (int ks = 0; ks < 8; ks++) {
            const int kk = ks * 8;
            unsigned af[4], bf[4][2];
            af[0] = Qs[r0 * QS_LD + kk + t];
            af[1] = Qs[r1 * QS_LD + kk + t];
            af[2] = Qs[r0 * QS_LD + kk + t + 4];
            af[3] = Qs[r1 * QS_LD + kk + t + 4];
            #pragma unroll
            for (int nt = 0; nt < 4; nt++) {
                int c = wn * 32 + nt * 8 + g;
                bf[nt][0] = Kc[c * KS_LD + kk + t];
                bf[nt][1] = Kc[c * KS_LD + kk + t + 4];
            }
            #pragma unroll
            for (int nt = 0; nt < 4; nt++)
                mma8(sacc[nt], af, bf[nt]);
        }

        // ---- causal mask on diagonal tile ----
        if (j0 == qt) {
            #pragma unroll
            for (int nt = 0; nt < 4; nt++) {
                int col = wn * 32 + nt * 8 + t * 2;
                if (col     > r0) sacc[nt][0] = -1e30f;
                if (col + 1 > r0) sacc[nt][1] = -1e30f;
                if (col     > r1) sacc[nt][2] = -1e30f;
                if (col + 1 > r1) sacc[nt][3] = -1e30f;
            }
        }

        // ---- register softmax: warp-partial max ----
        float tm0 = sacc[0][0], tm1 = sacc[0][2];
        #pragma unroll
        for (int nt = 0; nt < 4; nt++) {
            tm0 = fmaxf(tm0, fmaxf(sacc[nt][0], sacc[nt][1]));
            tm1 = fmaxf(tm1, fmaxf(sacc[nt][2], sacc[nt][3]));
        }
        tm0 = fmaxf(tm0, __shfl_xor_sync(0xffffffffu, tm0, 1));
        tm0 = fmaxf(tm0, __shfl_xor_sync(0xffffffffu, tm0, 2));
        tm1 = fmaxf(tm1, __shfl_xor_sync(0xffffffffu, tm1, 1));
        tm1 = fmaxf(tm1, __shfl_xor_sync(0xffffffffu, tm1, 2));
        if (t == 0) { pmax[r0 * 2 + wn] = tm0; pmax[r1 * 2 + wn] = tm1; }
        __syncthreads();

        const float mo0 = mrow[r0], mo1 = mrow[r1];
        const float mn0 = fmaxf(fmaxf(pmax[r0 * 2], pmax[r0 * 2 + 1]), mo0);
        const float mn1 = fmaxf(fmaxf(pmax[r1 * 2], pmax[r1 * 2 + 1]), mo1);
        const float al0 = __expf(mo0 - mn0);
        const float al1 = __expf(mo1 - mn1);

        float s0 = 0.f, s1 = 0.f;
        #pragma unroll
        for (int nt = 0; nt < 4; nt++) {
            float p00 = __expf(sacc[nt][0] - mn0);
            float p01 = __expf(sacc[nt][1] - mn0);
            float p10 = __expf(sacc[nt][2] - mn1);
            float p11 = __expf(sacc[nt][3] - mn1);
            s0 += p00 + p01;
            s1 += p10 + p11;
            int col = wn * 32 + nt * 8 + t * 2;
            *(uint2*)&Ps[r0 * PS_LD + col] = make_uint2(f2tf32(p00), f2tf32(p01));
            *(uint2*)&Ps[r1 * PS_LD + col] = make_uint2(f2tf32(p10), f2tf32(p11));
        }
        s0 += __shfl_xor_sync(0xffffffffu, s0, 1);
        s0 += __shfl_xor_sync(0xffffffffu, s0, 2);
        s1 += __shfl_xor_sync(0xffffffffu, s1, 1);
        s1 += __shfl_xor_sync(0xffffffffu, s1, 2);
        if (t == 0) { psum[r0 * 2 + wn] = s0; psum[r1 * 2 + wn] = s1; }

        // rescale O by alpha
        #pragma unroll
        for (int nt = 0; nt < 4; nt++) {
            o[nt][0] *= al0; o[nt][1] *= al0;
            o[nt][2] *= al1; o[nt][3] *= al1;
        }
        __syncthreads();

        // one thread per row: update running stats
        if (tid < 64) {
            int r = tid;
            float mo = mrow[r];
            float mn = fmaxf(fmaxf(pmax[r * 2], pmax[r * 2 + 1]), mo);
            float al = __expf(mo - mn);
            lrow[r] = lrow[r] * al + psum[r * 2] + psum[r * 2 + 1];
            mrow[r] = mn;
        }

        // ---- O += P @ V ----
        #pragma unroll
        for (int ks = 0; ks < 8; ks++) {
            const int kk = ks * 8;
            unsigned af[4], bf[4][2];
            af[0] = Ps[r0 * PS_LD + kk + t];
            af[1] = Ps[r1 * PS_LD + kk + t];
            af[2] = Ps[r0 * PS_LD + kk + t + 4];
            af[3] = Ps[r1 * PS_LD + kk + t + 4];
            #pragma unroll
            for (int nt = 0; nt < 4; nt++) {
                int c = wn * 32 + nt * 8 + g;
                bf[nt][0] = Vc[(kk + t) * VS_LD + c];
                bf[nt][1] = Vc[(kk + t + 4) * VS_LD + c];
            }
            #pragma unroll
            for (int nt = 0; nt < 4; nt++)
                mma8(o[nt], af, bf[nt]);
        }
        __syncthreads();   // protect Ks/Vs/Ps + stats before next tile
    }

    // ---- epilogue: normalize, store y as tf32 bits ----
    const float inv0 = 1.f / lrow[r0];
    const float inv1 = 1.f / lrow[r1];
    #pragma unroll
    for (int nt = 0; nt < 4; nt++) {
        int col = h * HD + wn * 32 + nt * 8 + t * 2;
        int rg = b * TT + qt * 64;
        *(uint2*)&g_y[(size_t)(rg + r0) * CC + col] =
            make_uint2(f2tf32(o[nt][0] * inv0), f2tf32(o[nt][1] * inv0));
        *(uint2*)&g_y[(size_t)(rg + r1) * CC + col] =
            make_uint2(f2tf32(o[nt][2] * inv1), f2tf32(o[nt][3] * inv1));
    }
#undef KV_ISSUE
}

// ---------------------------------------------------------------------------
extern "C" void kernel_launch(void* const* d_in, const int* in_sizes, int n_in,
                              void* d_out, int out_size)
{
    const float* x     = (const float*)d_in[0];
    const float* Wqkv  = (const float*)d_in[1];
    const float* bqkv  = (const float*)d_in[2];
    const float* Wproj = (const float*)d_in[3];
    const float* bproj = (const float*)d_in[4];
    float* out = (float*)d_out;

    cudaFuncSetAttribute(attn_kernel,
                         cudaFuncAttributeMaxDynamicSharedMemorySize,
                         ATTN_SMEM);

    float* xa; cudaGetSymbolAddress((void**)&xa, g_xa);
    float* wq; cudaGetSymbolAddress((void**)&wq, g_wqkva);
    float* wp; cudaGetSymbolAddress((void**)&wp, g_wproja);

    cvt_kernel<<<(BT*CC/4 + 255)/256, 256>>>(x, xa, BT*CC/4);
    cvt_kernel<<<(CC*N_QKV/4 + 255)/256, 256>>>(Wqkv, wq, CC*N_QKV/4);
    cvt_kernel<<<(CC*CC/4 + 255)/256, 256>>>(Wproj, wp, CC*CC/4);

    qkv_gemm_kernel<<<dim3(N_QKV / 128, BT / 128), 256>>>(xa, wq, bqkv);
    attn_kernel<<<dim3(TT / 64, NH, BB), 256, ATTN_SMEM>>>();
    proj_gemm_kernel<<<dim3(CC / 128, BT / 128), 256>>>(wp, bproj, out);
}

// round 9
// speedup vs baseline: 1.6295x; 1.6295x over previous
#include <cuda_runtime.h>
#include <cuda_bf16.h>

#define BB 4
#define TT 1024
#define CC 768
#define NH 12
#define HD 64
#define BT (BB*TT)
#define N_QKV (3*CC)

// Scratch: tf32 bit patterns in float arrays (q pre-scaled by 1/8).
__device__ __align__(256) float g_q[BB*NH*TT*HD];
__device__ __align__(256) float g_k[BB*NH*TT*HD];
__device__ __align__(256) float g_v[BB*NH*TT*HD];
__device__ __align__(256) float g_y[BT*CC];
__device__ __align__(256) float g_xa[BT*CC];
__device__ __align__(256) float g_wqkva[CC*N_QKV];
__device__ __align__(256) float g_wproja[CC*CC];

__device__ __forceinline__ unsigned f2tf32(float f) {
    unsigned r; asm("cvt.rna.tf32.f32 %0, %1;" : "=r"(r) : "f"(f)); return r;
}
__device__ __forceinline__ void mma8(float* c, const unsigned* a, const unsigned* b) {
    asm volatile(
        "mma.sync.aligned.m16n8k8.row.col.f32.tf32.tf32.f32 "
        "{%0,%1,%2,%3}, {%4,%5,%6,%7}, {%8,%9}, {%0,%1,%2,%3};"
        : "+f"(c[0]), "+f"(c[1]), "+f"(c[2]), "+f"(c[3])
        : "r"(a[0]), "r"(a[1]), "r"(a[2]), "r"(a[3]), "r"(b[0]), "r"(b[1]));
}
__device__ __forceinline__ unsigned smem_u32(const void* p) {
    return (unsigned)__cvta_generic_to_shared(p);
}
#define CPA(dst, src) asm volatile("cp.async.cg.shared.global [%0], [%1], 16;" :: "r"(dst), "l"(src))
#define CPC()  asm volatile("cp.async.commit_group;")
#define CPW0() asm volatile("cp.async.wait_group 0;")
#define CPW1() asm volatile("cp.async.wait_group 1;")

// ---------------------------------------------------------------------------
__global__ void cvt_kernel(const float* __restrict__ s, float* __restrict__ d, int n4)
{
    int i = blockIdx.x * blockDim.x + threadIdx.x;
    if (i < n4) {
        float4 v = ((const float4*)s)[i];
        ((uint4*)d)[i] = make_uint4(f2tf32(v.x), f2tf32(v.y), f2tf32(v.z), f2tf32(v.w));
    }
}

// ---------------------------------------------------------------------------
// GEMM mainloop: k-chunk 32, cp.async double-buffered (dynamic smem).
// C tile 128x128, 256 threads / 8 warps (2m x 4n).
// ---------------------------------------------------------------------------
#define GA_LD 36
#define GB_LD 136
#define ASZ (128*GA_LD)
#define BSZ (32*GB_LD)
#define GEMM_SMEM (2*(ASZ+BSZ)*4)

extern __shared__ unsigned dynsm[];

template<int N_GLOBAL>
__device__ __forceinline__ void gemm_mainloop_ca(
    const float* __restrict__ A, const float* __restrict__ Bm,
    int m0, int n0, float acc[4][4][4])
{
    unsigned* As = dynsm;
    unsigned* Bs = dynsm + 2*ASZ;
    const int tid  = threadIdx.x;
    const int warp = tid >> 5;
    const int lane = tid & 31;
    const int g = lane >> 2, t = lane & 3;
    const int wm = warp >> 2, wn = warp & 3;

    const unsigned aBase = smem_u32(As);
    const unsigned bBase = smem_u32(Bs);

    int aoff[4], boff[4];
    size_t asrc[4], bsrc[4];
    #pragma unroll
    for (int s = 0; s < 4; s++) {
        int idx = tid + s * 256;
        int ar = idx >> 3, ak = (idx & 7) * 4;
        aoff[s] = ar * GA_LD + ak;
        asrc[s] = (size_t)(m0 + ar) * CC + ak;
        int bk = idx >> 5, bn = (idx & 31) * 4;
        boff[s] = bk * GB_LD + bn;
        bsrc[s] = (size_t)bk * N_GLOBAL + n0 + bn;
    }

#define GEMM_ISSUE(k0, buf) do {                                                     \
        _Pragma("unroll")                                                            \
        for (int s = 0; s < 4; s++) {                                                \
            CPA(aBase + ((buf)*ASZ + aoff[s])*4u, A + asrc[s] + (k0));               \
            CPA(bBase + ((buf)*BSZ + boff[s])*4u, Bm + bsrc[s] + (size_t)(k0)*N_GLOBAL); \
        }                                                                            \
    } while (0)

    GEMM_ISSUE(0, 0);
    CPC();

    const int NIT = CC / 32;
    for (int it = 0; it < NIT; it++) {
        const int cur = it & 1;
        if (it + 1 < NIT) { GEMM_ISSUE((it + 1) * 32, cur ^ 1); CPC(); CPW1(); }
        else              { CPW0(); }
        __syncthreads();

        const unsigned* Ac = As + cur * ASZ;
        const unsigned* Bc = Bs + cur * BSZ;

        #pragma unroll
        for (int ks = 0; ks < 4; ks++) {
            const int kk = ks * 8;
            unsigned af[4][4], bf[4][2];
            #pragma unroll
            for (int mt = 0; mt < 4; mt++) {
                int r = wm * 64 + mt * 16 + g;
                af[mt][0] = Ac[r * GA_LD + kk + t];
                af[mt][1] = Ac[(r + 8) * GA_LD + kk + t];
                af[mt][2] = Ac[r * GA_LD + kk + t + 4];
                af[mt][3] = Ac[(r + 8) * GA_LD + kk + t + 4];
            }
            #pragma unroll
            for (int nt = 0; nt < 4; nt++) {
                int c = wn * 32 + nt * 8 + g;
                bf[nt][0] = Bc[(kk + t) * GB_LD + c];
                bf[nt][1] = Bc[(kk + t + 4) * GB_LD + c];
            }
            #pragma unroll
            for (int mt = 0; mt < 4; mt++)
                #pragma unroll
                for (int nt = 0; nt < 4; nt++)
                    mma8(acc[mt][nt], af[mt], bf[nt]);
        }
        __syncthreads();
    }
#undef GEMM_ISSUE
}

// ---------------------------------------------------------------------------
// Kernel 1: qkv = x @ Wqkv + bqkv -> head-major q/k/v (tf32 bits, q scaled)
// ---------------------------------------------------------------------------
__global__ __launch_bounds__(256, 2) void qkv_gemm_kernel(
    const float* __restrict__ A, const float* __restrict__ Bm,
    const float* __restrict__ bias)
{
    const int tid = threadIdx.x, warp = tid >> 5, lane = tid & 31;
    const int g = lane >> 2, t = lane & 3;
    const int wm = warp >> 2, wn = warp & 3;
    const int m0 = blockIdx.y * 128, n0 = blockIdx.x * 128;

    float acc[4][4][4];
    #pragma unroll
    for (int i = 0; i < 4; i++)
        #pragma unroll
        for (int j = 0; j < 4; j++)
            #pragma unroll
            for (int e = 0; e < 4; e++) acc[i][j][e] = 0.f;

    gemm_mainloop_ca<N_QKV>(A, Bm, m0, n0, acc);

    const int which = n0 / CC;
    float* dst = (which == 0) ? g_q : (which == 1) ? g_k : g_v;
    const float sc = (which == 0) ? 0.125f : 1.0f;

    #pragma unroll
    for (int mt = 0; mt < 4; mt++) {
        int r0 = m0 + wm * 64 + mt * 16 + g;
        #pragma unroll
        for (int nt = 0; nt < 4; nt++) {
            int cg = n0 + wn * 32 + nt * 8 + t * 2;
            int c0 = cg - which * CC;
            int h = c0 >> 6, d = c0 & 63;
            float b0v = bias[cg], b1v = bias[cg + 1];
            int b_ = r0 >> 10, t_ = r0 & 1023;
            *(uint2*)&dst[(size_t)(((b_ * NH + h) * TT) + t_) * HD + d] =
                make_uint2(f2tf32((acc[mt][nt][0] + b0v) * sc),
                           f2tf32((acc[mt][nt][1] + b1v) * sc));
            int r1 = r0 + 8;
            b_ = r1 >> 10; t_ = r1 & 1023;
            *(uint2*)&dst[(size_t)(((b_ * NH + h) * TT) + t_) * HD + d] =
                make_uint2(f2tf32((acc[mt][nt][2] + b0v) * sc),
                           f2tf32((acc[mt][nt][3] + b1v) * sc));
        }
    }
}

// ---------------------------------------------------------------------------
// Kernel 3: out = y @ Wproj + bproj (fp32 out)
// ---------------------------------------------------------------------------
__global__ __launch_bounds__(256, 2) void proj_gemm_kernel(
    const float* __restrict__ Bm, const float* __restrict__ bias,
    float* __restrict__ out)
{
    const int tid = threadIdx.x, warp = tid >> 5, lane = tid & 31;
    const int g = lane >> 2, t = lane & 3;
    const int wm = warp >> 2, wn = warp & 3;
    const int m0 = blockIdx.y * 128, n0 = blockIdx.x * 128;

    float acc[4][4][4];
    #pragma unroll
    for (int i = 0; i < 4; i++)
        #pragma unroll
        for (int j = 0; j < 4; j++)
            #pragma unroll
            for (int e = 0; e < 4; e++) acc[i][j][e] = 0.f;

    gemm_mainloop_ca<CC>(g_y, Bm, m0, n0, acc);

    #pragma unroll
    for (int mt = 0; mt < 4; mt++) {
        int r0 = m0 + wm * 64 + mt * 16 + g;
        #pragma unroll
        for (int nt = 0; nt < 4; nt++) {
            int cg = n0 + wn * 32 + nt * 8 + t * 2;
            float b0v = bias[cg], b1v = bias[cg + 1];
            *(float2*)&out[(size_t)r0 * CC + cg] =
                make_float2(acc[mt][nt][0] + b0v, acc[mt][nt][1] + b1v);
            *(float2*)&out[(size_t)(r0 + 8) * CC + cg] =
                make_float2(acc[mt][nt][2] + b0v, acc[mt][nt][3] + b1v);
        }
    }
}

// ---------------------------------------------------------------------------
// Kernel 2: causal flash attention. CTA = 128 q rows x (head, batch).
// 8 warps, each owns 16 rows x full 64-col key tile -> warp-local softmax
// (row stats in registers), P remapped C->A fragments via shuffles.
// One __syncthreads per key tile. K/V double-buffered cp.async.
// ---------------------------------------------------------------------------
#define QS_LD 68
#define KS_LD 68
#define VS_LD 72
#define OFF_K (128*QS_LD)
#define OFF_V (OFF_K + 2*64*KS_LD)
#define ATTN_SMEM ((OFF_V + 2*64*VS_LD) * 4)

__global__ __launch_bounds__(256) void attn_kernel()
{
    unsigned* Qs = dynsm;
    unsigned* Ks = dynsm + OFF_K;
    unsigned* Vs = dynsm + OFF_V;

    const int tid  = threadIdx.x;
    const int warp = tid >> 5;
    const int lane = tid & 31;
    const int g = lane >> 2, t = lane & 3;
    const int rm = warp * 16;
    const int r0 = rm + g, r1 = rm + g + 8;

    const int qt = gridDim.x - 1 - blockIdx.x;   // heavy tiles first
    const int h  = blockIdx.y;
    const int b  = blockIdx.z;

    const float* qb = g_q + (size_t)((b * NH + h) * TT) * HD;
    const float* kb = g_k + (size_t)((b * NH + h) * TT) * HD;
    const float* vb = g_v + (size_t)((b * NH + h) * TT) * HD;

    const unsigned qB = smem_u32(Qs);
    const unsigned kB = smem_u32(Ks);
    const unsigned vB = smem_u32(Vs);

    // loader maps
    int krw[4], kcc[4];
    #pragma unroll
    for (int s = 0; s < 4; s++) {
        int idx = tid + s * 256;
        krw[s] = idx >> 4;
        kcc[s] = (idx & 15) * 4;
    }

#define KV_ISSUE(j, buf) do {                                                   \
        _Pragma("unroll")                                                       \
        for (int s = 0; s < 4; s++) {                                           \
            size_t so = (size_t)((j) * 64 + krw[s]) * HD + kcc[s];              \
            CPA(kB + ((buf)*64*KS_LD + krw[s]*KS_LD + kcc[s])*4u, kb + so);     \
            CPA(vB + ((buf)*64*VS_LD + krw[s]*VS_LD + kcc[s])*4u, vb + so);     \
        }                                                                       \
    } while (0)

    // Prologue: Q (128 rows) + first K/V tile, one group
    #pragma unroll
    for (int s = 0; s < 8; s++) {
        int idx = tid + s * 256;
        int row = idx >> 4, c4 = (idx & 15) * 4;
        CPA(qB + (row * QS_LD + c4) * 4u, qb + (size_t)(qt * 128 + row) * HD + c4);
    }
    KV_ISSUE(0, 0);
    CPC();

    float mo0 = -1e30f, mo1 = -1e30f, lo0 = 0.f, lo1 = 0.f;
    float o[8][4];
    #pragma unroll
    for (int i = 0; i < 8; i++)
        #pragma unroll
        for (int e = 0; e < 4; e++) o[i][e] = 0.f;

    const int R0g = qt * 128 + r0;     // global q rows
    const int R1g = qt * 128 + r1;
    const unsigned srcA = (lane & 28) | ((lane & 3) >> 1);
    const unsigned srcB = srcA + 2;
    const bool selHi = (t & 1);

    const int NT = 2 * qt + 2;
    for (int j0 = 0; j0 < NT; j0++) {
        const int cur = j0 & 1;
        CPW0();
        __syncthreads();
        if (j0 + 1 < NT) { KV_ISSUE(j0 + 1, cur ^ 1); CPC(); }

        const unsigned* Kc = Ks + cur * 64 * KS_LD;
        const unsigned* Vc = Vs + cur * 64 * VS_LD;

        // ---- S = Q K^T : warp computes 16 x 64 ----
        float sacc[8][4];
        #pragma unroll
        for (int nt = 0; nt < 8; nt++)
            #pragma unroll
            for (int e = 0; e < 4; e++) sacc[nt][e] = 0.f;

        #pragma unroll
        for (int ks = 0; ks < 8; ks++) {
            const int kk = ks * 8;
            unsigned af[4];
            af[0] = Qs[r0 * QS_LD + kk + t];
            af[1] = Qs[r1 * QS_LD + kk + t];
            af[2] = Qs[r0 * QS_LD + kk + t + 4];
            af[3] = Qs[r1 * QS_LD + kk + t + 4];
            #pragma unroll
            for (int nt = 0; nt < 8; nt++) {
                unsigned bf[2];
                bf[0] = Kc[(nt * 8 + g) * KS_LD + kk + t];
                bf[1] = Kc[(nt * 8 + g) * KS_LD + kk + t + 4];
                mma8(sacc[nt], af, bf);
            }
        }

        // ---- causal mask (only tiles crossing the diagonal) ----
        if (j0 >= 2 * qt) {
            #pragma unroll
            for (int nt = 0; nt < 8; nt++) {
                int col = j0 * 64 + nt * 8 + t * 2;
                if (col     > R0g) sacc[nt][0] = -1e30f;
                if (col + 1 > R0g) sacc[nt][1] = -1e30f;
                if (col     > R1g) sacc[nt][2] = -1e30f;
                if (col + 1 > R1g) sacc[nt][3] = -1e30f;
            }
        }

        // ---- warp-local online softmax (stats in registers) ----
        float tm0 = sacc[0][0], tm1 = sacc[0][2];
        #pragma unroll
        for (int nt = 0; nt < 8; nt++) {
            tm0 = fmaxf(tm0, fmaxf(sacc[nt][0], sacc[nt][1]));
            tm1 = fmaxf(tm1, fmaxf(sacc[nt][2], sacc[nt][3]));
        }
        tm0 = fmaxf(tm0, __shfl_xor_sync(0xffffffffu, tm0, 1));
        tm0 = fmaxf(tm0, __shfl_xor_sync(0xffffffffu, tm0, 2));
        tm1 = fmaxf(tm1, __shfl_xor_sync(0xffffffffu, tm1, 1));
        tm1 = fmaxf(tm1, __shfl_xor_sync(0xffffffffu, tm1, 2));

        const float mn0 = fmaxf(mo0, tm0);
        const float mn1 = fmaxf(mo1, tm1);
        const float al0 = __expf(mo0 - mn0);
        const float al1 = __expf(mo1 - mn1);

        unsigned pu[8][4];
        float s0 = 0.f, s1 = 0.f;
        #pragma unroll
        for (int nt = 0; nt < 8; nt++) {
            float p00 = __expf(sacc[nt][0] - mn0);
            float p01 = __expf(sacc[nt][1] - mn0);
            float p10 = __expf(sacc[nt][2] - mn1);
            float p11 = __expf(sacc[nt][3] - mn1);
            s0 += p00 + p01; s1 += p10 + p11;
            pu[nt][0] = f2tf32(p00); pu[nt][1] = f2tf32(p01);
            pu[nt][2] = f2tf32(p10); pu[nt][3] = f2tf32(p11);
        }
        s0 += __shfl_xor_sync(0xffffffffu, s0, 1);
        s0 += __shfl_xor_sync(0xffffffffu, s0, 2);
        s1 += __shfl_xor_sync(0xffffffffu, s1, 1);
        s1 += __shfl_xor_sync(0xffffffffu, s1, 2);
        lo0 = lo0 * al0 + s0;  mo0 = mn0;
        lo1 = lo1 * al1 + s1;  mo1 = mn1;

        #pragma unroll
        for (int dt = 0; dt < 8; dt++) {
            o[dt][0] *= al0; o[dt][1] *= al0;
            o[dt][2] *= al1; o[dt][3] *= al1;
        }

        // ---- O += P @ V : C-fragment -> A-fragment via shuffles ----
        #pragma unroll
        for (int kc = 0; kc < 8; kc++) {
            unsigned af[4];
            unsigned v0, v1;
            v0 = __shfl_sync(0xffffffffu, pu[kc][0], srcA);
            v1 = __shfl_sync(0xffffffffu, pu[kc][1], srcA);
            af[0] = selHi ? v1 : v0;
            v0 = __shfl_sync(0xffffffffu, pu[kc][2], srcA);
            v1 = __shfl_sync(0xffffffffu, pu[kc][3], srcA);
            af[1] = selHi ? v1 : v0;
            v0 = __shfl_sync(0xffffffffu, pu[kc][0], srcB);
            v1 = __shfl_sync(0xffffffffu, pu[kc][1], srcB);
            af[2] = selHi ? v1 : v0;
            v0 = __shfl_sync(0xffffffffu, pu[kc][2], srcB);
            v1 = __shfl_sync(0xffffffffu, pu[kc][3], srcB);
            af[3] = selHi ? v1 : v0;
            #pragma unroll
            for (int dt = 0; dt < 8; dt++) {
                unsigned bf[2];
                bf[0] = Vc[(kc * 8 + t) * VS_LD + dt * 8 + g];
                bf[1] = Vc[(kc * 8 + t + 4) * VS_LD + dt * 8 + g];
                mma8(o[dt], af, bf);
            }
        }
    }

    // ---- epilogue: normalize, store y as tf32 bits ----
    const float inv0 = 1.f / lo0;
    const float inv1 = 1.f / lo1;
    #pragma unroll
    for (int dt = 0; dt < 8; dt++) {
        int col = h * HD + dt * 8 + t * 2;
        *(uint2*)&g_y[(size_t)(b * TT + R0g) * CC + col] =
            make_uint2(f2tf32(o[dt][0] * inv0), f2tf32(o[dt][1] * inv0));
        *(uint2*)&g_y[(size_t)(b * TT + R1g) * CC + col] =
            make_uint2(f2tf32(o[dt][2] * inv1), f2tf32(o[dt][3] * inv1));
    }
#undef KV_ISSUE
}

// ---------------------------------------------------------------------------
extern "C" void kernel_launch(void* const* d_in, const int* in_sizes, int n_in,
                              void* d_out, int out_size)
{
    const float* x     = (const float*)d_in[0];
    const float* Wqkv  = (const float*)d_in[1];
    const float* bqkv  = (const float*)d_in[2];
    const float* Wproj = (const float*)d_in[3];
    const float* bproj = (const float*)d_in[4];
    float* out = (float*)d_out;

    cudaFuncSetAttribute(attn_kernel, cudaFuncAttributeMaxDynamicSharedMemorySize, ATTN_SMEM);
    cudaFuncSetAttribute(qkv_gemm_kernel, cudaFuncAttributeMaxDynamicSharedMemorySize, GEMM_SMEM);
    cudaFuncSetAttribute(proj_gemm_kernel, cudaFuncAttributeMaxDynamicSharedMemorySize, GEMM_SMEM);

    float* xa; cudaGetSymbolAddress((void**)&xa, g_xa);
    float* wq; cudaGetSymbolAddress((void**)&wq, g_wqkva);
    float* wp; cudaGetSymbolAddress((void**)&wp, g_wproja);

    cvt_kernel<<<(BT*CC/4 + 255)/256, 256>>>(x, xa, BT*CC/4);
    cvt_kernel<<<(CC*N_QKV/4 + 255)/256, 256>>>(Wqkv, wq, CC*N_QKV/4);
    cvt_kernel<<<(CC*CC/4 + 255)/256, 256>>>(Wproj, wp, CC*CC/4);

    qkv_gemm_kernel<<<dim3(N_QKV/128, BT/128), 256, GEMM_SMEM>>>(xa, wq, bqkv);
    attn_kernel<<<dim3(TT/128, NH, BB), 256, ATTN_SMEM>>>();
    proj_gemm_kernel<<<dim3(CC/128, BT/128), 256, GEMM_SMEM>>>(wp, bproj, out);
}

// round 10
// speedup vs baseline: 1.7021x; 1.0445x over previous
#include <cuda_runtime.h>
#include <cuda_bf16.h>

#define BB 4
#define TT 1024
#define CC 768
#define NH 12
#define HD 64
#define BT (BB*TT)
#define N_QKV (3*CC)

// Scratch: tf32 bit patterns in float arrays (q pre-scaled by log2e/8).
__device__ __align__(256) float g_q[BB*NH*TT*HD];
__device__ __align__(256) float g_k[BB*NH*TT*HD];
__device__ __align__(256) float g_v[BB*NH*TT*HD];
__device__ __align__(256) float g_y[BT*CC];
__device__ __align__(256) float g_xa[BT*CC];
__device__ __align__(256) float g_wqkva[CC*N_QKV];
__device__ __align__(256) float g_wproja[CC*CC];

__device__ __forceinline__ unsigned f2tf32(float f) {
    unsigned r; asm("cvt.rna.tf32.f32 %0, %1;" : "=r"(r) : "f"(f)); return r;
}
__device__ __forceinline__ float ex2(float x) {
    float r; asm("ex2.approx.ftz.f32 %0, %1;" : "=f"(r) : "f"(x)); return r;
}
__device__ __forceinline__ void mma8(float* c, const unsigned* a, const unsigned* b) {
    asm volatile(
        "mma.sync.aligned.m16n8k8.row.col.f32.tf32.tf32.f32 "
        "{%0,%1,%2,%3}, {%4,%5,%6,%7}, {%8,%9}, {%0,%1,%2,%3};"
        : "+f"(c[0]), "+f"(c[1]), "+f"(c[2]), "+f"(c[3])
        : "r"(a[0]), "r"(a[1]), "r"(a[2]), "r"(a[3]), "r"(b[0]), "r"(b[1]));
}
__device__ __forceinline__ unsigned smem_u32(const void* p) {
    return (unsigned)__cvta_generic_to_shared(p);
}
#define CPA(dst, src) asm volatile("cp.async.cg.shared.global [%0], [%1], 16;" :: "r"(dst), "l"(src))
#define CPC()  asm volatile("cp.async.commit_group;")
#define CPW0() asm volatile("cp.async.wait_group 0;")
#define CPW1() asm volatile("cp.async.wait_group 1;")

// ---------------------------------------------------------------------------
__global__ void cvt_kernel(const float* __restrict__ s, float* __restrict__ d, int n4)
{
    int i = blockIdx.x * blockDim.x + threadIdx.x;
    if (i < n4) {
        float4 v = ((const float4*)s)[i];
        ((uint4*)d)[i] = make_uint4(f2tf32(v.x), f2tf32(v.y), f2tf32(v.z), f2tf32(v.w));
    }
}

// ---------------------------------------------------------------------------
// GEMM mainloop: k-chunk 32, cp.async 3-stage, ONE sync per k-iter.
// C tile 128x128, 256 threads / 8 warps (2m x 4n).
// ---------------------------------------------------------------------------
#define GA_LD 36
#define GB_LD 136
#define ASZ (128*GA_LD)
#define BSZ (32*GB_LD)
#define GEMM_SMEM (3*(ASZ+BSZ)*4)

extern __shared__ unsigned dynsm[];

template<int N_GLOBAL>
__device__ __forceinline__ void gemm_mainloop_ca(
    const float* __restrict__ A, const float* __restrict__ Bm,
    int m0, int n0, float acc[4][4][4])
{
    unsigned* As = dynsm;
    unsigned* Bs = dynsm + 3*ASZ;
    const int tid  = threadIdx.x;
    const int warp = tid >> 5;
    const int lane = tid & 31;
    const int g = lane >> 2, t = lane & 3;
    const int wm = warp >> 2, wn = warp & 3;

    const unsigned aBase = smem_u32(As);
    const unsigned bBase = smem_u32(Bs);

    int aoff[4], boff[4];
    size_t asrc[4], bsrc[4];
    #pragma unroll
    for (int s = 0; s < 4; s++) {
        int idx = tid + s * 256;
        int ar = idx >> 3, ak = (idx & 7) * 4;
        aoff[s] = ar * GA_LD + ak;
        asrc[s] = (size_t)(m0 + ar) * CC + ak;
        int bk = idx >> 5, bn = (idx & 31) * 4;
        boff[s] = bk * GB_LD + bn;
        bsrc[s] = (size_t)bk * N_GLOBAL + n0 + bn;
    }

#define GEMM_ISSUE(k0, buf) do {                                                     \
        _Pragma("unroll")                                                            \
        for (int s = 0; s < 4; s++) {                                                \
            CPA(aBase + ((buf)*ASZ + aoff[s])*4u, A + asrc[s] + (k0));               \
            CPA(bBase + ((buf)*BSZ + boff[s])*4u, Bm + bsrc[s] + (size_t)(k0)*N_GLOBAL); \
        }                                                                            \
    } while (0)

    GEMM_ISSUE(0, 0);
    CPC();
    GEMM_ISSUE(32, 1);
    CPC();

    const int NIT = CC / 32;
    int buf = 0;
    for (int it = 0; it < NIT; it++) {
        if (it < NIT - 1) CPW1(); else CPW0();
        __syncthreads();
        if (it + 2 < NIT) {
            int nb = buf + 2; if (nb >= 3) nb -= 3;
            GEMM_ISSUE((it + 2) * 32, nb);
            CPC();
        }

        const unsigned* Ac = As + buf * ASZ;
        const unsigned* Bc = Bs + buf * BSZ;

        #pragma unroll
        for (int ks = 0; ks < 4; ks++) {
            const int kk = ks * 8;
            unsigned af[4][4], bf[4][2];
            #pragma unroll
            for (int mt = 0; mt < 4; mt++) {
                int r = wm * 64 + mt * 16 + g;
                af[mt][0] = Ac[r * GA_LD + kk + t];
                af[mt][1] = Ac[(r + 8) * GA_LD + kk + t];
                af[mt][2] = Ac[r * GA_LD + kk + t + 4];
                af[mt][3] = Ac[(r + 8) * GA_LD + kk + t + 4];
            }
            #pragma unroll
            for (int nt = 0; nt < 4; nt++) {
                int c = wn * 32 + nt * 8 + g;
                bf[nt][0] = Bc[(kk + t) * GB_LD + c];
                bf[nt][1] = Bc[(kk + t + 4) * GB_LD + c];
            }
            #pragma unroll
            for (int mt = 0; mt < 4; mt++)
                #pragma unroll
                for (int nt = 0; nt < 4; nt++)
                    mma8(acc[mt][nt], af[mt], bf[nt]);
        }
        if (++buf == 3) buf = 0;
    }
#undef GEMM_ISSUE
}

// ---------------------------------------------------------------------------
// Kernel 1: qkv = x @ Wqkv + bqkv -> head-major q/k/v (tf32 bits,
// q pre-scaled by log2e/8 for exp2-domain softmax)
// ---------------------------------------------------------------------------
__global__ __launch_bounds__(256, 2) void qkv_gemm_kernel(
    const float* __restrict__ A, const float* __restrict__ Bm,
    const float* __restrict__ bias)
{
    const int tid = threadIdx.x, warp = tid >> 5, lane = tid & 31;
    const int g = lane >> 2, t = lane & 3;
    const int wm = warp >> 2, wn = warp & 3;
    const int m0 = blockIdx.y * 128, n0 = blockIdx.x * 128;

    float acc[4][4][4];
    #pragma unroll
    for (int i = 0; i < 4; i++)
        #pragma unroll
        for (int j = 0; j < 4; j++)
            #pragma unroll
            for (int e = 0; e < 4; e++) acc[i][j][e] = 0.f;

    gemm_mainloop_ca<N_QKV>(A, Bm, m0, n0, acc);

    const int which = n0 / CC;
    float* dst = (which == 0) ? g_q : (which == 1) ? g_k : g_v;
    const float sc = (which == 0) ? (0.125f * 1.4426950408889634f) : 1.0f;

    #pragma unroll
    for (int mt = 0; mt < 4; mt++) {
        int r0 = m0 + wm * 64 + mt * 16 + g;
        #pragma unroll
        for (int nt = 0; nt < 4; nt++) {
            int cg = n0 + wn * 32 + nt * 8 + t * 2;
            int c0 = cg - which * CC;
            int h = c0 >> 6, d = c0 & 63;
            float b0v = bias[cg], b1v = bias[cg + 1];
            int b_ = r0 >> 10, t_ = r0 & 1023;
            *(uint2*)&dst[(size_t)(((b_ * NH + h) * TT) + t_) * HD + d] =
                make_uint2(f2tf32((acc[mt][nt][0] + b0v) * sc),
                           f2tf32((acc[mt][nt][1] + b1v) * sc));
            int r1 = r0 + 8;
            b_ = r1 >> 10; t_ = r1 & 1023;
            *(uint2*)&dst[(size_t)(((b_ * NH + h) * TT) + t_) * HD + d] =
                make_uint2(f2tf32((acc[mt][nt][2] + b0v) * sc),
                           f2tf32((acc[mt][nt][3] + b1v) * sc));
        }
    }
}

// ---------------------------------------------------------------------------
// Kernel 3: out = y @ Wproj + bproj (fp32 out)
// ---------------------------------------------------------------------------
__global__ __launch_bounds__(256, 2) void proj_gemm_kernel(
    const float* __restrict__ Bm, const float* __restrict__ bias,
    float* __restrict__ out)
{
    const int tid = threadIdx.x, warp = tid >> 5, lane = tid & 31;
    const int g = lane >> 2, t = lane & 3;
    const int wm = warp >> 2, wn = warp & 3;
    const int m0 = blockIdx.y * 128, n0 = blockIdx.x * 128;

    float acc[4][4][4];
    #pragma unroll
    for (int i = 0; i < 4; i++)
        #pragma unroll
        for (int j = 0; j < 4; j++)
            #pragma unroll
            for (int e = 0; e < 4; e++) acc[i][j][e] = 0.f;

    gemm_mainloop_ca<CC>(g_y, Bm, m0, n0, acc);

    #pragma unroll
    for (int mt = 0; mt < 4; mt++) {
        int r0 = m0 + wm * 64 + mt * 16 + g;
        #pragma unroll
        for (int nt = 0; nt < 4; nt++) {
            int cg = n0 + wn * 32 + nt * 8 + t * 2;
            float b0v = bias[cg], b1v = bias[cg + 1];
            *(float2*)&out[(size_t)r0 * CC + cg] =
                make_float2(acc[mt][nt][0] + b0v, acc[mt][nt][1] + b1v);
            *(float2*)&out[(size_t)(r0 + 8) * CC + cg] =
                make_float2(acc[mt][nt][2] + b0v, acc[mt][nt][3] + b1v);
        }
    }
}

// ---------------------------------------------------------------------------
// Kernel 2: causal flash attention. CTA = 128 q rows x (head, batch).
// 8 warps x (16 rows x 64 cols); warp-local softmax in exp2 domain;
// P tf32 bits stored back into sacc (register reuse); C->A remap via shuffles.
// One __syncthreads per key tile; 2 CTAs/SM.
// ---------------------------------------------------------------------------
#define QS_LD 68
#define KS_LD 68
#define VS_LD 72
#define OFF_K (128*QS_LD)
#define OFF_V (OFF_K + 2*64*KS_LD)
#define ATTN_SMEM ((OFF_V + 2*64*VS_LD) * 4)

__global__ __launch_bounds__(256, 2) void attn_kernel()
{
    unsigned* Qs = dynsm;
    unsigned* Ks = dynsm + OFF_K;
    unsigned* Vs = dynsm + OFF_V;

    const int tid  = threadIdx.x;
    const int warp = tid >> 5;
    const int lane = tid & 31;
    const int g = lane >> 2, t = lane & 3;
    const int rm = warp * 16;
    const int r0 = rm + g, r1 = rm + g + 8;

    const int qt = gridDim.x - 1 - blockIdx.x;   // heavy tiles first
    const int h  = blockIdx.y;
    const int b  = blockIdx.z;

    const float* qb = g_q + (size_t)((b * NH + h) * TT) * HD;
    const float* kb = g_k + (size_t)((b * NH + h) * TT) * HD;
    const float* vb = g_v + (size_t)((b * NH + h) * TT) * HD;

    const unsigned qB = smem_u32(Qs);
    const unsigned kB = smem_u32(Ks);
    const unsigned vB = smem_u32(Vs);

    int krw[4], kcc[4];
    #pragma unroll
    for (int s = 0; s < 4; s++) {
        int idx = tid + s * 256;
        krw[s] = idx >> 4;
        kcc[s] = (idx & 15) * 4;
    }

#define KV_ISSUE(j, buf) do {                                                   \
        _Pragma("unroll")                                                       \
        for (int s = 0; s < 4; s++) {                                           \
            size_t so = (size_t)((j) * 64 + krw[s]) * HD + kcc[s];              \
            CPA(kB + ((buf)*64*KS_LD + krw[s]*KS_LD + kcc[s])*4u, kb + so);     \
            CPA(vB + ((buf)*64*VS_LD + krw[s]*VS_LD + kcc[s])*4u, vb + so);     \
        }                                                                       \
    } while (0)

    #pragma unroll
    for (int s = 0; s < 8; s++) {
        int idx = tid + s * 256;
        int row = idx >> 4, c4 = (idx & 15) * 4;
        CPA(qB + (row * QS_LD + c4) * 4u, qb + (size_t)(qt * 128 + row) * HD + c4);
    }
    KV_ISSUE(0, 0);
    CPC();

    float mo0 = -1e30f, mo1 = -1e30f, lo0 = 0.f, lo1 = 0.f;
    float o[8][4];
    #pragma unroll
    for (int i = 0; i < 8; i++)
        #pragma unroll
        for (int e = 0; e < 4; e++) o[i][e] = 0.f;

    const int R0g = qt * 128 + r0;
    const int R1g = qt * 128 + r1;
    const unsigned srcA = (lane & 28) | ((lane & 3) >> 1);
    const unsigned srcB = srcA + 2;
    const bool selHi = (t & 1);

    const int NT = 2 * qt + 2;
    for (int j0 = 0; j0 < NT; j0++) {
        const int cur = j0 & 1;
        CPW0();
        __syncthreads();
        if (j0 + 1 < NT) { KV_ISSUE(j0 + 1, cur ^ 1); CPC(); }

        const unsigned* Kc = Ks + cur * 64 * KS_LD;
        const unsigned* Vc = Vs + cur * 64 * VS_LD;

        // ---- S = Q K^T (log2e pre-folded into q) ----
        float sacc[8][4];
        #pragma unroll
        for (int nt = 0; nt < 8; nt++)
            #pragma unroll
            for (int e = 0; e < 4; e++) sacc[nt][e] = 0.f;

        #pragma unroll
        for (int ks = 0; ks < 8; ks++) {
            const int kk = ks * 8;
            unsigned af[4];
            af[0] = Qs[r0 * QS_LD + kk + t];
            af[1] = Qs[r1 * QS_LD + kk + t];
            af[2] = Qs[r0 * QS_LD + kk + t + 4];
            af[3] = Qs[r1 * QS_LD + kk + t + 4];
            #pragma unroll
            for (int nt = 0; nt < 8; nt++) {
                unsigned bf[2];
                bf[0] = Kc[(nt * 8 + g) * KS_LD + kk + t];
                bf[1] = Kc[(nt * 8 + g) * KS_LD + kk + t + 4];
                mma8(sacc[nt], af, bf);
            }
        }

        if (j0 >= 2 * qt) {
            #pragma unroll
            for (int nt = 0; nt < 8; nt++) {
                int col = j0 * 64 + nt * 8 + t * 2;
                if (col     > R0g) sacc[nt][0] = -1e30f;
                if (col + 1 > R0g) sacc[nt][1] = -1e30f;
                if (col     > R1g) sacc[nt][2] = -1e30f;
                if (col + 1 > R1g) sacc[nt][3] = -1e30f;
            }
        }

        // ---- warp-local online softmax (exp2 domain; stats in regs) ----
        float tm0 = sacc[0][0], tm1 = sacc[0][2];
        #pragma unroll
        for (int nt = 0; nt < 8; nt++) {
            tm0 = fmaxf(tm0, fmaxf(sacc[nt][0], sacc[nt][1]));
            tm1 = fmaxf(tm1, fmaxf(sacc[nt][2], sacc[nt][3]));
        }
        tm0 = fmaxf(tm0, __shfl_xor_sync(0xffffffffu, tm0, 1));
        tm0 = fmaxf(tm0, __shfl_xor_sync(0xffffffffu, tm0, 2));
        tm1 = fmaxf(tm1, __shfl_xor_sync(0xffffffffu, tm1, 1));
        tm1 = fmaxf(tm1, __shfl_xor_sync(0xffffffffu, tm1, 2));

        const float mn0 = fmaxf(mo0, tm0);
        const float mn1 = fmaxf(mo1, tm1);
        const float al0 = ex2(mo0 - mn0);
        const float al1 = ex2(mo1 - mn1);

        float s0 = 0.f, s1 = 0.f;
        #pragma unroll
        for (int nt = 0; nt < 8; nt++) {
            float p00 = ex2(sacc[nt][0] - mn0);
            float p01 = ex2(sacc[nt][1] - mn0);
            float p10 = ex2(sacc[nt][2] - mn1);
            float p11 = ex2(sacc[nt][3] - mn1);
            s0 += p00 + p01; s1 += p10 + p11;
            sacc[nt][0] = __uint_as_float(f2tf32(p00));
            sacc[nt][1] = __uint_as_float(f2tf32(p01));
            sacc[nt][2] = __uint_as_float(f2tf32(p10));
            sacc[nt][3] = __uint_as_float(f2tf32(p11));
        }
        s0 += __shfl_xor_sync(0xffffffffu, s0, 1);
        s0 += __shfl_xor_sync(0xffffffffu, s0, 2);
        s1 += __shfl_xor_sync(0xffffffffu, s1, 1);
        s1 += __shfl_xor_sync(0xffffffffu, s1, 2);
        lo0 = lo0 * al0 + s0;  mo0 = mn0;
        lo1 = lo1 * al1 + s1;  mo1 = mn1;

        #pragma unroll
        for (int dt = 0; dt < 8; dt++) {
            o[dt][0] *= al0; o[dt][1] *= al0;
            o[dt][2] *= al1; o[dt][3] *= al1;
        }

        // ---- O += P @ V : C-fragment -> A-fragment via shuffles ----
        #pragma unroll
        for (int kc = 0; kc < 8; kc++) {
            unsigned af[4];
            unsigned v0, v1;
            v0 = __shfl_sync(0xffffffffu, __float_as_uint(sacc[kc][0]), srcA);
            v1 = __shfl_sync(0xffffffffu, __float_as_uint(sacc[kc][1]), srcA);
            af[0] = selHi ? v1 : v0;
            v0 = __shfl_sync(0xffffffffu, __float_as_uint(sacc[kc][2]), srcA);
            v1 = __shfl_sync(0xffffffffu, __float_as_uint(sacc[kc][3]), srcA);
            af[1] = selHi ? v1 : v0;
            v0 = __shfl_sync(0xffffffffu, __float_as_uint(sacc[kc][0]), srcB);
            v1 = __shfl_sync(0xffffffffu, __float_as_uint(sacc[kc][1]), srcB);
            af[2] = selHi ? v1 : v0;
            v0 = __shfl_sync(0xffffffffu, __float_as_uint(sacc[kc][2]), srcB);
            v1 = __shfl_sync(0xffffffffu, __float_as_uint(sacc[kc][3]), srcB);
            af[3] = selHi ? v1 : v0;
            #pragma unroll
            for (int dt = 0; dt < 8; dt++) {
                unsigned bf[2];
                bf[0] = Vc[(kc * 8 + t) * VS_LD + dt * 8 + g];
                bf[1] = Vc[(kc * 8 + t + 4) * VS_LD + dt * 8 + g];
                mma8(o[dt], af, bf);
            }
        }
    }

    // ---- epilogue: normalize, store y as tf32 bits ----
    const float inv0 = 1.f / lo0;
    const float inv1 = 1.f / lo1;
    #pragma unroll
    for (int dt = 0; dt < 8; dt++) {
        int col = h * HD + dt * 8 + t * 2;
        *(uint2*)&g_y[(size_t)(b * TT + R0g) * CC + col] =
            make_uint2(f2tf32(o[dt][0] * inv0), f2tf32(o[dt][1] * inv0));
        *(uint2*)&g_y[(size_t)(b * TT + R1g) * CC + col] =
            make_uint2(f2tf32(o[dt][2] * inv1), f2tf32(o[dt][3] * inv1));
    }
#undef KV_ISSUE
}

// ---------------------------------------------------------------------------
extern "C" void kernel_launch(void* const* d_in, const int* in_sizes, int n_in,
                              void* d_out, int out_size)
{
    const float* x     = (const float*)d_in[0];
    const float* Wqkv  = (const float*)d_in[1];
    const float* bqkv  = (const float*)d_in[2];
    const float* Wproj = (const float*)d_in[3];
    const float* bproj = (const float*)d_in[4];
    float* out = (float*)d_out;

    cudaFuncSetAttribute(attn_kernel, cudaFuncAttributeMaxDynamicSharedMemorySize, ATTN_SMEM);
    cudaFuncSetAttribute(qkv_gemm_kernel, cudaFuncAttributeMaxDynamicSharedMemorySize, GEMM_SMEM);
    cudaFuncSetAttribute(proj_gemm_kernel, cudaFuncAttributeMaxDynamicSharedMemorySize, GEMM_SMEM);

    float* xa; cudaGetSymbolAddress((void**)&xa, g_xa);
    float* wq; cudaGetSymbolAddress((void**)&wq, g_wqkva);
    float* wp; cudaGetSymbolAddress((void**)&wp, g_wproja);

    cvt_kernel<<<(BT*CC/4 + 255)/256, 256>>>(x, xa, BT*CC/4);
    cvt_kernel<<<(CC*N_QKV/4 + 255)/256, 256>>>(Wqkv, wq, CC*N_QKV/4);
    cvt_kernel<<<(CC*CC/4 + 255)/256, 256>>>(Wproj, wp, CC*CC/4);

    qkv_gemm_kernel<<<dim3(N_QKV/128, BT/128), 256, GEMM_SMEM>>>(xa, wq, bqkv);
    attn_kernel<<<dim3(TT/128, NH, BB), 256, ATTN_SMEM>>>();
    proj_gemm_kernel<<<dim3(CC/128, BT/128), 256, GEMM_SMEM>>>(wp, bproj, out);
}

// round 11
// speedup vs baseline: 1.7817x; 1.0468x over previous
#include <cuda_runtime.h>
#include <cuda_bf16.h>

#define BB 4
#define TT 1024
#define CC 768
#define NH 12
#define HD 64
#define BT (BB*TT)
#define N_QKV (3*CC)

// Scratch: tf32 bit patterns (q pre-scaled by log2e/8). g_v is D-MAJOR [B,NH,HD,TT].
__device__ __align__(256) float g_q[BB*NH*TT*HD];
__device__ __align__(256) float g_k[BB*NH*TT*HD];
__device__ __align__(256) float g_v[BB*NH*HD*TT];
__device__ __align__(256) float g_y[BT*CC];
__device__ __align__(256) float g_xa[BT*CC];
__device__ __align__(256) float g_wqt[N_QKV*CC];   // Wqkv transposed [N][K]
__device__ __align__(256) float g_wpt[CC*CC];      // Wproj transposed [N][K]

__device__ __forceinline__ unsigned f2tf32(float f) {
    unsigned r; asm("cvt.rna.tf32.f32 %0, %1;" : "=r"(r) : "f"(f)); return r;
}
__device__ __forceinline__ float ex2(float x) {
    float r; asm("ex2.approx.ftz.f32 %0, %1;" : "=f"(r) : "f"(x)); return r;
}
__device__ __forceinline__ void mma8(float* c, const unsigned* a, const unsigned* b) {
    asm volatile(
        "mma.sync.aligned.m16n8k8.row.col.f32.tf32.tf32.f32 "
        "{%0,%1,%2,%3}, {%4,%5,%6,%7}, {%8,%9}, {%0,%1,%2,%3};"
        : "+f"(c[0]), "+f"(c[1]), "+f"(c[2]), "+f"(c[3])
        : "r"(a[0]), "r"(a[1]), "r"(a[2]), "r"(a[3]), "r"(b[0]), "r"(b[1]));
}
__device__ __forceinline__ unsigned smem_u32(const void* p) {
    return (unsigned)__cvta_generic_to_shared(p);
}
#define CPA(dst, src) asm volatile("cp.async.cg.shared.global [%0], [%1], 16;" :: "r"(dst), "l"(src))
#define CPC()  asm volatile("cp.async.commit_group;")
#define CPW0() asm volatile("cp.async.wait_group 0;")
#define CPW1() asm volatile("cp.async.wait_group 1;")
#define LDSM4(d0,d1,d2,d3,a) \
    asm volatile("ldmatrix.sync.aligned.m8n8.x4.shared.b16 {%0,%1,%2,%3}, [%4];" \
                 : "=r"(d0),"=r"(d1),"=r"(d2),"=r"(d3) : "r"(a))

// ---------------------------------------------------------------------------
__global__ void cvt_kernel(const float* __restrict__ s, float* __restrict__ d, int n4)
{
    int i = blockIdx.x * blockDim.x + threadIdx.x;
    if (i < n4) {
        float4 v = ((const float4*)s)[i];
        ((uint4*)d)[i] = make_uint4(f2tf32(v.x), f2tf32(v.y), f2tf32(v.z), f2tf32(v.w));
    }
}

// Transpose + tf32 cvt: W [K][N] fp32 -> Wt [N][K=CC] tf32 bits
__global__ void tcvt_kernel(const float* __restrict__ W, float* __restrict__ Wt, int N)
{
    __shared__ float t[32][33];
    int n0 = blockIdx.x * 32, k0 = blockIdx.y * 32;
    int tx = threadIdx.x, ty = threadIdx.y;  // 32 x 8
    #pragma unroll
    for (int i = 0; i < 4; i++)
        t[ty + i*8][tx] = W[(size_t)(k0 + ty + i*8) * N + n0 + tx];
    __syncthreads();
    #pragma unroll
    for (int i = 0; i < 4; i++)
        Wt[(size_t)(n0 + ty + i*8) * CC + k0 + tx] =
            __uint_as_float(f2tf32(t[tx][ty + i*8]));
}

// ---------------------------------------------------------------------------
// GEMM mainloop: k-chunk 32, 3-stage cp.async, ldmatrix fragment loads.
// A and B tiles both [128 rows][32 k], LD=36. 256 threads / 8 warps (2m x 4n).
// ---------------------------------------------------------------------------
#define GLD 36
#define TSZ (128*GLD)
#define GEMM_SMEM (3*2*TSZ*4)

extern __shared__ unsigned dynsm[];

__device__ __forceinline__ void gemm_mainloop(
    const float* __restrict__ A, const float* __restrict__ Bm,
    int m0, int n0, float acc[4][4][4])
{
    unsigned* As = dynsm;
    unsigned* Bs = dynsm + 3*TSZ;
    const int tid  = threadIdx.x;
    const int warp = tid >> 5;
    const int lane = tid & 31;
    const int wm = warp >> 2, wn = warp & 3;

    const unsigned aBase = smem_u32(As);
    const unsigned bBase = smem_u32(Bs);

    int off[4];
    size_t asrc[4], bsrc[4];
    #pragma unroll
    for (int s = 0; s < 4; s++) {
        int idx = tid + s * 256;
        int row = idx >> 3, k4 = (idx & 7) * 4;
        off[s] = row * GLD + k4;
        asrc[s] = (size_t)(m0 + row) * CC + k4;
        bsrc[s] = (size_t)(n0 + row) * CC + k4;
    }

    // ldmatrix per-lane addresses
    const int a_r = lane & 15, a_c = (lane >> 4) * 4;
    const int b_r = (lane & 7) + ((lane & 16) >> 1);
    const int b_c = (lane & 8) ? 4 : 0;
    unsigned aAd[4], bAd[2];
    #pragma unroll
    for (int mt = 0; mt < 4; mt++)
        aAd[mt] = aBase + ((wm*64 + mt*16 + a_r) * GLD + a_c) * 4;
    #pragma unroll
    for (int np = 0; np < 2; np++)
        bAd[np] = bBase + ((wn*32 + np*16 + b_r) * GLD + b_c) * 4;

#define GEMM_ISSUE(k0, buf) do {                                         \
        _Pragma("unroll")                                                \
        for (int s = 0; s < 4; s++) {                                    \
            CPA(aBase + ((buf)*TSZ + off[s])*4u, A + asrc[s] + (k0));    \
            CPA(bBase + ((buf)*TSZ + off[s])*4u, Bm + bsrc[s] + (k0));   \
        }                                                                \
    } while (0)

    GEMM_ISSUE(0, 0);  CPC();
    GEMM_ISSUE(32, 1); CPC();

    const int NIT = CC / 32;
    int buf = 0;
    for (int it = 0; it < NIT; it++) {
        if (it < NIT - 1) CPW1(); else CPW0();
        __syncthreads();
        if (it + 2 < NIT) {
            int nb = buf + 2; if (nb >= 3) nb -= 3;
            GEMM_ISSUE((it + 2) * 32, nb);
            CPC();
        }

        const unsigned ab = (unsigned)(buf * TSZ * 4);
        #pragma unroll
        for (int ks = 0; ks < 4; ks++) {
            const unsigned kb = ab + ks * 32;
            unsigned af[4][4], bf[4][2];
            #pragma unroll
            for (int mt = 0; mt < 4; mt++)
                LDSM4(af[mt][0], af[mt][1], af[mt][2], af[mt][3], aAd[mt] + kb);
            LDSM4(bf[0][0], bf[0][1], bf[1][0], bf[1][1], bAd[0] + kb);
            LDSM4(bf[2][0], bf[2][1], bf[3][0], bf[3][1], bAd[1] + kb);
            #pragma unroll
            for (int mt = 0; mt < 4; mt++)
                #pragma unroll
                for (int nt = 0; nt < 4; nt++)
                    mma8(acc[mt][nt], af[mt], bf[nt]);
        }
        if (++buf == 3) buf = 0;
    }
#undef GEMM_ISSUE
}

// ---------------------------------------------------------------------------
// Kernel 1: qkv -> q/k token-major (q pre-scaled log2e/8), v D-MAJOR
// ---------------------------------------------------------------------------
__global__ __launch_bounds__(256, 2) void qkv_gemm_kernel(const float* __restrict__ bias)
{
    const int tid = threadIdx.x, warp = tid >> 5, lane = tid & 31;
    const int g = lane >> 2, t = lane & 3;
    const int wm = warp >> 2, wn = warp & 3;
    const int m0 = blockIdx.y * 128, n0 = blockIdx.x * 128;

    float acc[4][4][4];
    #pragma unroll
    for (int i = 0; i < 4; i++)
        #pragma unroll
        for (int j = 0; j < 4; j++)
            #pragma unroll
            for (int e = 0; e < 4; e++) acc[i][j][e] = 0.f;

    gemm_mainloop(g_xa, g_wqt, m0, n0, acc);

    const int which = n0 / CC;
    const float sc = (which == 0) ? (0.125f * 1.4426950408889634f) : 1.0f;

    #pragma unroll
    for (int mt = 0; mt < 4; mt++) {
        int r0 = m0 + wm * 64 + mt * 16 + g;
        #pragma unroll
        for (int nt = 0; nt < 4; nt++) {
            int cg = n0 + wn * 32 + nt * 8 + t * 2;
            int c0 = cg - which * CC;
            int h = c0 >> 6, d = c0 & 63;
            float b0v = bias[cg], b1v = bias[cg + 1];
            int ba = r0 >> 10, ta = r0 & 1023;
            int bb_ = (r0 + 8) >> 10, tb = (r0 + 8) & 1023;
            if (which == 2) {   // v: d-major [B,NH,HD,TT]
                float* vb_ = g_v + (size_t)((ba * NH + h) * HD) * TT;
                float* vb2 = g_v + (size_t)((bb_ * NH + h) * HD) * TT;
                vb_[(size_t)d * TT + ta]       = __uint_as_float(f2tf32(acc[mt][nt][0] + b0v));
                vb_[(size_t)(d+1) * TT + ta]   = __uint_as_float(f2tf32(acc[mt][nt][1] + b1v));
                vb2[(size_t)d * TT + tb]       = __uint_as_float(f2tf32(acc[mt][nt][2] + b0v));
                vb2[(size_t)(d+1) * TT + tb]   = __uint_as_float(f2tf32(acc[mt][nt][3] + b1v));
            } else {
                float* dst = (which == 0) ? g_q : g_k;
                *(uint2*)&dst[(size_t)(((ba * NH + h) * TT) + ta) * HD + d] =
                    make_uint2(f2tf32((acc[mt][nt][0] + b0v) * sc),
                               f2tf32((acc[mt][nt][1] + b1v) * sc));
                *(uint2*)&dst[(size_t)(((bb_ * NH + h) * TT) + tb) * HD + d] =
                    make_uint2(f2tf32((acc[mt][nt][2] + b0v) * sc),
                               f2tf32((acc[mt][nt][3] + b1v) * sc));
            }
        }
    }
}

// ---------------------------------------------------------------------------
// Kernel 3: out = y @ Wproj + bproj (fp32 out)
// ---------------------------------------------------------------------------
__global__ __launch_bounds__(256, 2) void proj_gemm_kernel(const float* __restrict__ bias,
                                                           float* __restrict__ out)
{
    const int tid = threadIdx.x, warp = tid >> 5, lane = tid & 31;
    const int g = lane >> 2, t = lane & 3;
    const int wm = warp >> 2, wn = warp & 3;
    const int m0 = blockIdx.y * 128, n0 = blockIdx.x * 128;

    float acc[4][4][4];
    #pragma unroll
    for (int i = 0; i < 4; i++)
        #pragma unroll
        for (int j = 0; j < 4; j++)
            #pragma unroll
            for (int e = 0; e < 4; e++) acc[i][j][e] = 0.f;

    gemm_mainloop(g_y, g_wpt, m0, n0, acc);

    #pragma unroll
    for (int mt = 0; mt < 4; mt++) {
        int r0 = m0 + wm * 64 + mt * 16 + g;
        #pragma unroll
        for (int nt = 0; nt < 4; nt++) {
            int cg = n0 + wn * 32 + nt * 8 + t * 2;
            float b0v = bias[cg], b1v = bias[cg + 1];
            *(float2*)&out[(size_t)r0 * CC + cg] =
                make_float2(acc[mt][nt][0] + b0v, acc[mt][nt][1] + b1v);
            *(float2*)&out[(size_t)(r0 + 8) * CC + cg] =
                make_float2(acc[mt][nt][2] + b0v, acc[mt][nt][3] + b1v);
        }
    }
}

// ---------------------------------------------------------------------------
// Kernel 2: causal flash attention, ldmatrix fragments for Q/K/V.
// CTA = 128 q rows x (head, batch). 8 warps x (16 rows x 64 cols).
// ---------------------------------------------------------------------------
#define QS_LD 68
#define KS_LD 68
#define VS_LD 68
#define OFF_K (128*QS_LD)
#define OFF_V (OFF_K + 2*64*KS_LD)
#define ATTN_SMEM ((OFF_V + 2*64*VS_LD) * 4)

__global__ __launch_bounds__(256, 2) void attn_kernel()
{
    unsigned* Qs = dynsm;
    const int tid  = threadIdx.x;
    const int warp = tid >> 5;
    const int lane = tid & 31;
    const int g = lane >> 2, t = lane & 3;
    const int rm = warp * 16;
    const int r0 = rm + g, r1 = rm + g + 8;

    const int qt = gridDim.x - 1 - blockIdx.x;
    const int h  = blockIdx.y;
    const int b  = blockIdx.z;

    const float* qb = g_q + (size_t)((b * NH + h) * TT) * HD;
    const float* kb = g_k + (size_t)((b * NH + h) * TT) * HD;
    const float* vb = g_v + (size_t)((b * NH + h) * HD) * TT;   // d-major

    const unsigned qB = smem_u32(Qs);
    const unsigned kB = qB + OFF_K * 4;
    const unsigned vB = qB + OFF_V * 4;

    // ldmatrix lane maps
    const int a_r = lane & 15, a_c = (lane >> 4) * 4;
    const int b_r = (lane & 7) + ((lane & 16) >> 1);
    const int b_c = (lane & 8) ? 4 : 0;
    const unsigned qAd = qB + ((rm + a_r) * QS_LD + a_c) * 4;
    unsigned kAd[4], vAd[4];
    #pragma unroll
    for (int j = 0; j < 4; j++) {
        kAd[j] = kB + ((j*16 + b_r) * KS_LD + b_c) * 4;
        vAd[j] = vB + ((j*16 + b_r) * VS_LD + b_c) * 4;
    }

    int krw[4], kcc[4];
    #pragma unroll
    for (int s = 0; s < 4; s++) {
        int idx = tid + s * 256;
        krw[s] = idx >> 4;
        kcc[s] = (idx & 15) * 4;
    }

#define KV_ISSUE(j, bufo) do {                                                       \
        _Pragma("unroll")                                                            \
        for (int s = 0; s < 4; s++) {                                                \
            CPA(kB + ((bufo)*64*KS_LD + krw[s]*KS_LD + kcc[s])*4u,                   \
                kb + (size_t)((j) * 64 + krw[s]) * HD + kcc[s]);                     \
            CPA(vB + ((bufo)*64*VS_LD + krw[s]*VS_LD + kcc[s])*4u,                   \
                vb + (size_t)krw[s] * TT + (j) * 64 + kcc[s]);                       \
        }                                                                            \
    } while (0)

    #pragma unroll
    for (int s = 0; s < 8; s++) {
        int idx = tid + s * 256;
        int row = idx >> 4, c4 = (idx & 15) * 4;
        CPA(qB + (row * QS_LD + c4) * 4u, qb + (size_t)(qt * 128 + row) * HD + c4);
    }
    KV_ISSUE(0, 0);
    CPC();

    float mo0 = -1e30f, mo1 = -1e30f, lo0 = 0.f, lo1 = 0.f;
    float o[8][4];
    #pragma unroll
    for (int i = 0; i < 8; i++)
        #pragma unroll
        for (int e = 0; e < 4; e++) o[i][e] = 0.f;

    const int R0g = qt * 128 + r0;
    const int R1g = qt * 128 + r1;
    const unsigned srcA = (lane & 28) | ((lane & 3) >> 1);
    const unsigned srcB = srcA + 2;
    const bool selHi = (t & 1);

    const int NT = 2 * qt + 2;
    for (int j0 = 0; j0 < NT; j0++) {
        const int cur = j0 & 1;
        CPW0();
        __syncthreads();
        if (j0 + 1 < NT) { KV_ISSUE(j0 + 1, cur ^ 1); CPC(); }

        const unsigned kbo = (unsigned)(cur * 64 * KS_LD * 4);
        const unsigned vbo = (unsigned)(cur * 64 * VS_LD * 4);

        // ---- S = Q K^T ----
        float sacc[8][4];
        #pragma unroll
        for (int nt = 0; nt < 8; nt++)
            #pragma unroll
            for (int e = 0; e < 4; e++) sacc[nt][e] = 0.f;

        #pragma unroll
        for (int ks = 0; ks < 8; ks++) {
            const unsigned kk4 = ks * 32;
            unsigned af[4], bf[8][2];
            LDSM4(af[0], af[1], af[2], af[3], qAd + kk4);
            #pragma unroll
            for (int j = 0; j < 4; j++)
                LDSM4(bf[2*j][0], bf[2*j][1], bf[2*j+1][0], bf[2*j+1][1],
                      kAd[j] + kbo + kk4);
            #pragma unroll
            for (int nt = 0; nt < 8; nt++)
                mma8(sacc[nt], af, bf[nt]);
        }

        if (j0 >= 2 * qt) {
            #pragma unroll
            for (int nt = 0; nt < 8; nt++) {
                int col = j0 * 64 + nt * 8 + t * 2;
                if (col     > R0g) sacc[nt][0] = -1e30f;
                if (col + 1 > R0g) sacc[nt][1] = -1e30f;
                if (col     > R1g) sacc[nt][2] = -1e30f;
                if (col + 1 > R1g) sacc[nt][3] = -1e30f;
            }
        }

        // ---- warp-local online softmax (exp2 domain) ----
        float tm0 = sacc[0][0], tm1 = sacc[0][2];
        #pragma unroll
        for (int nt = 0; nt < 8; nt++) {
            tm0 = fmaxf(tm0, fmaxf(sacc[nt][0], sacc[nt][1]));
            tm1 = fmaxf(tm1, fmaxf(sacc[nt][2], sacc[nt][3]));
        }
        tm0 = fmaxf(tm0, __shfl_xor_sync(0xffffffffu, tm0, 1));
        tm0 = fmaxf(tm0, __shfl_xor_sync(0xffffffffu, tm0, 2));
        tm1 = fmaxf(tm1, __shfl_xor_sync(0xffffffffu, tm1, 1));
        tm1 = fmaxf(tm1, __shfl_xor_sync(0xffffffffu, tm1, 2));

        const float mn0 = fmaxf(mo0, tm0);
        const float mn1 = fmaxf(mo1, tm1);
        const float al0 = ex2(mo0 - mn0);
        const float al1 = ex2(mo1 - mn1);

        float s0 = 0.f, s1 = 0.f;
        #pragma unroll
        for (int nt = 0; nt < 8; nt++) {
            float p00 = ex2(sacc[nt][0] - mn0);
            float p01 = ex2(sacc[nt][1] - mn0);
            float p10 = ex2(sacc[nt][2] - mn1);
            float p11 = ex2(sacc[nt][3] - mn1);
            s0 += p00 + p01; s1 += p10 + p11;
            sacc[nt][0] = __uint_as_float(f2tf32(p00));
            sacc[nt][1] = __uint_as_float(f2tf32(p01));
            sacc[nt][2] = __uint_as_float(f2tf32(p10));
            sacc[nt][3] = __uint_as_float(f2tf32(p11));
        }
        s0 += __shfl_xor_sync(0xffffffffu, s0, 1);
        s0 += __shfl_xor_sync(0xffffffffu, s0, 2);
        s1 += __shfl_xor_sync(0xffffffffu, s1, 1);
        s1 += __shfl_xor_sync(0xffffffffu, s1, 2);
        lo0 = lo0 * al0 + s0;  mo0 = mn0;
        lo1 = lo1 * al1 + s1;  mo1 = mn1;

        #pragma unroll
        for (int dt = 0; dt < 8; dt++) {
            o[dt][0] *= al0; o[dt][1] *= al0;
            o[dt][2] *= al1; o[dt][3] *= al1;
        }

        // ---- O += P @ V ----
        #pragma unroll
        for (int kc = 0; kc < 8; kc++) {
            unsigned af[4], bf[8][2];
            unsigned v0, v1;
            v0 = __shfl_sync(0xffffffffu, __float_as_uint(sacc[kc][0]), srcA);
            v1 = __shfl_sync(0xffffffffu, __float_as_uint(sacc[kc][1]), srcA);
            af[0] = selHi ? v1 : v0;
            v0 = __shfl_sync(0xffffffffu, __float_as_uint(sacc[kc][2]), srcA);
            v1 = __shfl_sync(0xffffffffu, __float_as_uint(sacc[kc][3]), srcA);
            af[1] = selHi ? v1 : v0;
            v0 = __shfl_sync(0xffffffffu, __float_as_uint(sacc[kc][0]), srcB);
            v1 = __shfl_sync(0xffffffffu, __float_as_uint(sacc[kc][1]), srcB);
            af[2] = selHi ? v1 : v0;
            v0 = __shfl_sync(0xffffffffu, __float_as_uint(sacc[kc][2]), srcB);
            v1 = __shfl_sync(0xffffffffu, __float_as_uint(sacc[kc][3]), srcB);
            af[3] = selHi ? v1 : v0;
            #pragma unroll
            for (int j = 0; j < 4; j++)
                LDSM4(bf[2*j][0], bf[2*j][1], bf[2*j+1][0], bf[2*j+1][1],
                      vAd[j] + vbo + kc * 32);
            #pragma unroll
            for (int dt = 0; dt < 8; dt++)
                mma8(o[dt], af, bf[dt]);
        }
    }

    // ---- epilogue: normalize, store y as tf32 bits ----
    const float inv0 = 1.f / lo0;
    const float inv1 = 1.f / lo1;
    #pragma unroll
    for (int dt = 0; dt < 8; dt++) {
        int col = h * HD + dt * 8 + t * 2;
        *(uint2*)&g_y[(size_t)(b * TT + R0g) * CC + col] =
            make_uint2(f2tf32(o[dt][0] * inv0), f2tf32(o[dt][1] * inv0));
        *(uint2*)&g_y[(size_t)(b * TT + R1g) * CC + col] =
            make_uint2(f2tf32(o[dt][2] * inv1), f2tf32(o[dt][3] * inv1));
    }
#undef KV_ISSUE
}

// ---------------------------------------------------------------------------
extern "C" void kernel_launch(void* const* d_in, const int* in_sizes, int n_in,
                              void* d_out, int out_size)
{
    const float* x     = (const float*)d_in[0];
    const float* Wqkv  = (const float*)d_in[1];
    const float* bqkv  = (const float*)d_in[2];
    const float* Wproj = (const float*)d_in[3];
    const float* bproj = (const float*)d_in[4];
    float* out = (float*)d_out;

    cudaFuncSetAttribute(attn_kernel, cudaFuncAttributeMaxDynamicSharedMemorySize, ATTN_SMEM);
    cudaFuncSetAttribute(qkv_gemm_kernel, cudaFuncAttributeMaxDynamicSharedMemorySize, GEMM_SMEM);
    cudaFuncSetAttribute(proj_gemm_kernel, cudaFuncAttributeMaxDynamicSharedMemorySize, GEMM_SMEM);

    float* xa; cudaGetSymbolAddress((void**)&xa, g_xa);
    float* wq; cudaGetSymbolAddress((void**)&wq, g_wqt);
    float* wp; cudaGetSymbolAddress((void**)&wp, g_wpt);

    cvt_kernel<<<(BT*CC/4 + 255)/256, 256>>>(x, xa, BT*CC/4);
    tcvt_kernel<<<dim3(N_QKV/32, CC/32), dim3(32, 8)>>>(Wqkv, wq, N_QKV);
    tcvt_kernel<<<dim3(CC/32, CC/32), dim3(32, 8)>>>(Wproj, wp, CC);

    qkv_gemm_kernel<<<dim3(N_QKV/128, BT/128), 256, GEMM_SMEM>>>(bqkv);
    attn_kernel<<<dim3(TT/128, NH, BB), 256, ATTN_SMEM>>>();
    proj_gemm_kernel<<<dim3(CC/128, BT/128), 256, GEMM_SMEM>>>(bproj, out);
}